// round 1
// baseline (speedup 1.0000x reference)
#include <cuda_runtime.h>
#include <cuda_bf16.h>
#include <cstdint>

// Problem constants
#define BATCH     8192
#define DIM       256
#define TGT       16384          // 2*BATCH targets (pos ++ neg)
#define INV_TEMP  20.0f          // 1 / 0.05

// GEMM tiling
#define BM        128            // anchor rows per CTA
#define BN        128            // target cols per inner tile
#define BK        64             // k-chunk for B streaming
#define PADA      132            // padded smem row stride (floats), 16B-friendly
#define PADB      132
#define COLSPLIT  4              // column splits -> partial (m,s) per split
#define COLS_PER_SPLIT (TGT / COLSPLIT)        // 4096
#define CT_PER_SPLIT   (COLS_PER_SPLIT / BN)   // 32
#define SMEM_FLOATS (DIM * PADA + BK * PADB)   // 33792 + 8448
#define SMEM_BYTES  (SMEM_FLOATS * 4)          // 168960 B

// ---------------- scratch (device globals: allocation-free) ----------------
__device__ float g_anorm[BATCH * DIM];                 // 8 MB
__device__ float g_tnorm[TGT * DIM];                   // 16 MB
__device__ float g_diag [BATCH];                       // scaled diagonal logits
__device__ float g_pm   [COLSPLIT * BATCH];            // partial running max
__device__ float g_ps   [COLSPLIT * BATCH];            // partial sum-exp

// ---------------- f32x2 packed math helpers ----------------
__device__ __forceinline__ unsigned long long pack2(float x, float y) {
    unsigned long long r;
    asm("mov.b64 %0, {%1, %2};" : "=l"(r) : "f"(x), "f"(y));
    return r;
}
__device__ __forceinline__ void fma2(unsigned long long& d,
                                     unsigned long long a,
                                     unsigned long long b) {
    asm("fma.rn.f32x2 %0, %1, %2, %0;" : "+l"(d) : "l"(a), "l"(b));
}
__device__ __forceinline__ float lo32(unsigned long long u) {
    return __uint_as_float((unsigned int)(u & 0xffffffffull));
}
__device__ __forceinline__ float hi32(unsigned long long u) {
    return __uint_as_float((unsigned int)(u >> 32));
}

// ---------------- kernel 1: L2-normalize all 24576 rows ----------------
// warp per row; anchor -> g_anorm, pos -> g_tnorm[0:8192), neg -> g_tnorm[8192:16384)
__global__ void k_normalize(const float* __restrict__ A,
                            const float* __restrict__ P,
                            const float* __restrict__ N) {
    int gw   = (blockIdx.x * blockDim.x + threadIdx.x) >> 5;
    int lane = threadIdx.x & 31;
    if (gw >= 3 * BATCH) return;

    const float* src;
    float* dst;
    if (gw < BATCH)            { src = A + (size_t)gw * DIM;            dst = g_anorm + (size_t)gw * DIM; }
    else if (gw < 2 * BATCH)   { src = P + (size_t)(gw - BATCH) * DIM;  dst = g_tnorm + (size_t)(gw - BATCH) * DIM; }
    else                       { src = N + (size_t)(gw - 2*BATCH)*DIM;  dst = g_tnorm + (size_t)(gw - BATCH) * DIM; }

    float4 v0 = ((const float4*)src)[lane];
    float4 v1 = ((const float4*)src)[lane + 32];
    float s = v0.x*v0.x + v0.y*v0.y + v0.z*v0.z + v0.w*v0.w
            + v1.x*v1.x + v1.y*v1.y + v1.z*v1.z + v1.w*v1.w;
    #pragma unroll
    for (int o = 16; o; o >>= 1) s += __shfl_xor_sync(0xffffffffu, s, o);
    float inv = 1.0f / fmaxf(sqrtf(s), 1e-12f);

    v0.x *= inv; v0.y *= inv; v0.z *= inv; v0.w *= inv;
    v1.x *= inv; v1.y *= inv; v1.z *= inv; v1.w *= inv;
    ((float4*)dst)[lane]      = v0;
    ((float4*)dst)[lane + 32] = v1;
}

// ---------------- kernel 2: diagonal logits from RAW inputs ----------------
// diag[i] = (a_i . p_i) / (max(|a_i|,eps) * max(|p_i|,eps)) * INV_TEMP
__global__ void k_diag(const float* __restrict__ A, const float* __restrict__ P) {
    int gw   = (blockIdx.x * blockDim.x + threadIdx.x) >> 5;
    int lane = threadIdx.x & 31;
    if (gw >= BATCH) return;
    const float* a = A + (size_t)gw * DIM;
    const float* p = P + (size_t)gw * DIM;
    float4 a0 = ((const float4*)a)[lane], a1 = ((const float4*)a)[lane + 32];
    float4 p0 = ((const float4*)p)[lane], p1 = ((const float4*)p)[lane + 32];
    float saa = a0.x*a0.x + a0.y*a0.y + a0.z*a0.z + a0.w*a0.w
              + a1.x*a1.x + a1.y*a1.y + a1.z*a1.z + a1.w*a1.w;
    float spp = p0.x*p0.x + p0.y*p0.y + p0.z*p0.z + p0.w*p0.w
              + p1.x*p1.x + p1.y*p1.y + p1.z*p1.z + p1.w*p1.w;
    float sap = a0.x*p0.x + a0.y*p0.y + a0.z*p0.z + a0.w*p0.w
              + a1.x*p1.x + a1.y*p1.y + a1.z*p1.z + a1.w*p1.w;
    #pragma unroll
    for (int o = 16; o; o >>= 1) {
        saa += __shfl_xor_sync(0xffffffffu, saa, o);
        spp += __shfl_xor_sync(0xffffffffu, spp, o);
        sap += __shfl_xor_sync(0xffffffffu, sap, o);
    }
    if (lane == 0) {
        float d = sap / (fmaxf(sqrtf(saa), 1e-12f) * fmaxf(sqrtf(spp), 1e-12f));
        g_diag[gw] = d * INV_TEMP;
    }
}

// ---------------- kernel 3: fused GEMM + online logsumexp ----------------
// grid (COLSPLIT, BATCH/BM). Block: 256 threads, 16x16 layout, 8x8 microtile
// with packed f32x2 accumulators. A tile (128x256 fp32) resident in smem.
__global__ void __launch_bounds__(256, 1) k_gemm_lse() {
    extern __shared__ float sm[];
    float* a_s = sm;                    // [DIM][PADA]  (k-major, transposed)
    float* b_s = sm + DIM * PADA;       // [BK][PADB]

    const int tid  = threadIdx.x;
    const int tx   = tid & 15;
    const int ty   = tid >> 4;
    const int row0 = blockIdx.y * BM;
    const int col0 = blockIdx.x * COLS_PER_SPLIT;

    // load A tile once: a_s[k][row]
    #pragma unroll
    for (int i = 0; i < 32; ++i) {
        int idx = tid + 256 * i;
        int k4  = idx >> 7;            // 0..63
        int row = idx & 127;
        float4 v = *(const float4*)(g_anorm + (size_t)(row0 + row) * DIM + k4 * 4);
        a_s[(k4*4 + 0) * PADA + row] = v.x;
        a_s[(k4*4 + 1) * PADA + row] = v.y;
        a_s[(k4*4 + 2) * PADA + row] = v.z;
        a_s[(k4*4 + 3) * PADA + row] = v.w;
    }

    float run_m[8], run_s[8];
    #pragma unroll
    for (int r = 0; r < 8; ++r) { run_m[r] = -3.402823466e38f; run_s[r] = 0.0f; }

    for (int ct = 0; ct < CT_PER_SPLIT; ++ct) {
        unsigned long long acc2[8][4];
        #pragma unroll
        for (int r = 0; r < 8; ++r)
            #pragma unroll
            for (int c = 0; c < 4; ++c) acc2[r][c] = 0ull;

        const int cbase = col0 + ct * BN;

        for (int kt = 0; kt < DIM / BK; ++kt) {
            __syncthreads();   // previous compute done (also covers A load, 1st iter)
            // load B chunk: b_s[k][col], k in [0,64)
            #pragma unroll
            for (int i = 0; i < 8; ++i) {
                int idx = tid + 256 * i;
                int k4  = idx >> 7;        // 0..15
                int col = idx & 127;
                float4 v = *(const float4*)(g_tnorm + (size_t)(cbase + col) * DIM
                                            + kt * BK + k4 * 4);
                b_s[(k4*4 + 0) * PADB + col] = v.x;
                b_s[(k4*4 + 1) * PADB + col] = v.y;
                b_s[(k4*4 + 2) * PADB + col] = v.z;
                b_s[(k4*4 + 3) * PADB + col] = v.w;
            }
            __syncthreads();

            #pragma unroll 8
            for (int k = 0; k < BK; ++k) {
                const int kk = kt * BK + k;
                float4 a0 = *(const float4*)&a_s[kk * PADA + ty * 8];
                float4 a1 = *(const float4*)&a_s[kk * PADA + ty * 8 + 4];
                ulonglong2 b01 = *(const ulonglong2*)&b_s[k * PADB + tx * 8];
                ulonglong2 b23 = *(const ulonglong2*)&b_s[k * PADB + tx * 8 + 4];
                unsigned long long bb0 = b01.x, bb1 = b01.y, bb2 = b23.x, bb3 = b23.y;
                float ar[8] = {a0.x, a0.y, a0.z, a0.w, a1.x, a1.y, a1.z, a1.w};
                #pragma unroll
                for (int r = 0; r < 8; ++r) {
                    unsigned long long a2 = pack2(ar[r], ar[r]);
                    fma2(acc2[r][0], a2, bb0);
                    fma2(acc2[r][1], a2, bb1);
                    fma2(acc2[r][2], a2, bb2);
                    fma2(acc2[r][3], a2, bb3);
                }
            }
        }

        // ---- online LSE epilogue for this 128-col tile ----
        #pragma unroll
        for (int r = 0; r < 8; ++r) {
            float sc[8];
            #pragma unroll
            for (int cp = 0; cp < 4; ++cp) {
                sc[2*cp]     = lo32(acc2[r][cp]) * INV_TEMP;
                sc[2*cp + 1] = hi32(acc2[r][cp]) * INV_TEMP;
            }
            float tmax = sc[0];
            #pragma unroll
            for (int c = 1; c < 8; ++c) tmax = fmaxf(tmax, sc[c]);
            #pragma unroll
            for (int o = 1; o <= 8; o <<= 1)
                tmax = fmaxf(tmax, __shfl_xor_sync(0xffffffffu, tmax, o));
            float nm = fmaxf(run_m[r], tmax);
            float ls = 0.0f;
            #pragma unroll
            for (int c = 0; c < 8; ++c) ls += __expf(sc[c] - nm);
            #pragma unroll
            for (int o = 1; o <= 8; o <<= 1)
                ls += __shfl_xor_sync(0xffffffffu, ls, o);
            run_s[r] = run_s[r] * __expf(run_m[r] - nm) + ls;
            run_m[r] = nm;
        }
    }

    if (tx == 0) {
        #pragma unroll
        for (int r = 0; r < 8; ++r) {
            int row = row0 + ty * 8 + r;
            g_pm[blockIdx.x * BATCH + row] = run_m[r];
            g_ps[blockIdx.x * BATCH + row] = run_s[r];
        }
    }
}

// ---------------- kernel 4: combine splits, mean loss ----------------
__global__ void k_final(float* __restrict__ out) {
    __shared__ double sd[256];
    double acc = 0.0;
    for (int row = threadIdx.x; row < BATCH; row += 256) {
        float m = g_pm[row];
        #pragma unroll
        for (int j = 1; j < COLSPLIT; ++j) m = fmaxf(m, g_pm[j * BATCH + row]);
        float s = 0.0f;
        #pragma unroll
        for (int j = 0; j < COLSPLIT; ++j)
            s += g_ps[j * BATCH + row] * __expf(g_pm[j * BATCH + row] - m);
        float lse = m + __logf(s);
        acc += (double)(lse - g_diag[row]);
    }
    sd[threadIdx.x] = acc;
    __syncthreads();
    #pragma unroll
    for (int s = 128; s > 0; s >>= 1) {
        if (threadIdx.x < s) sd[threadIdx.x] += sd[threadIdx.x + s];
        __syncthreads();
    }
    if (threadIdx.x == 0) out[0] = (float)(sd[0] / (double)BATCH);
}

// ---------------- launcher ----------------
extern "C" void kernel_launch(void* const* d_in, const int* in_sizes, int n_in,
                              void* d_out, int out_size) {
    const float* A = (const float*)d_in[0];   // embedding_anchor
    const float* P = (const float*)d_in[1];   // embedding_pos
    const float* N = (const float*)d_in[2];   // embedding_neg
    float* out = (float*)d_out;

    cudaFuncSetAttribute(k_gemm_lse, cudaFuncAttributeMaxDynamicSharedMemorySize,
                         SMEM_BYTES);

    k_normalize<<<(3 * BATCH) / 8, 256>>>(A, P, N);   // 8 warps/block
    k_diag<<<BATCH / 8, 256>>>(A, P);
    k_gemm_lse<<<dim3(COLSPLIT, BATCH / BM), 256, SMEM_BYTES>>>();
    k_final<<<1, 256>>>(out);
}

// round 3
// speedup vs baseline: 5.8054x; 5.8054x over previous
#include <cuda_runtime.h>
#include <cuda_bf16.h>
#include <cstdint>

// ---------------- problem constants ----------------
#define BATCH 8192
#define DIM   256
#define TGT   16384
#define COLSPLIT 2
#define COLS_PER_SPLIT (TGT / COLSPLIT)   // 8192
#define NTILES (COLS_PER_SPLIT / 128)     // 64 B-tiles per CTA
#define SCALE_A 28.8539008177792681f      // (1/0.05) * log2(e)
#define LN2_D   0.69314718055994530942

// ---------------- scratch (device globals) ----------------
__device__ __nv_bfloat16 g_an[BATCH * DIM];   // normalized anchor * SCALE_A
__device__ __nv_bfloat16 g_tn[TGT * DIM];     // normalized targets
__device__ float  g_diag[BATCH];              // exact base-2 diag logits
__device__ float  g_ps[4 * BATCH];            // partial sum-exp2 (colsplit x warp_n)
__device__ double g_bsum[32];

// ---------------- helpers ----------------
__device__ __forceinline__ uint32_t smem_u32(const void* p) {
    uint32_t a;
    asm("{ .reg .u64 t; cvta.to.shared.u64 t, %1; cvt.u32.u64 %0, t; }" : "=r"(a) : "l"(p));
    return a;
}
__device__ __forceinline__ float ex2f(float x) {
    float y; asm("ex2.approx.f32 %0, %1;" : "=f"(y) : "f"(x)); return y;
}
__device__ __forceinline__ void cp16(uint32_t dst, const void* src) {
    asm volatile("cp.async.cg.shared.global [%0], [%1], 16;" :: "r"(dst), "l"(src));
}
__device__ __forceinline__ void ldsm_x4(uint32_t* r, uint32_t addr) {
    asm volatile("ldmatrix.sync.aligned.m8n8.x4.shared.b16 {%0,%1,%2,%3}, [%4];"
        : "=r"(r[0]), "=r"(r[1]), "=r"(r[2]), "=r"(r[3]) : "r"(addr));
}
__device__ __forceinline__ void mma16816(float* d, const uint32_t* a, const uint32_t* b) {
    asm volatile("mma.sync.aligned.m16n8k16.row.col.f32.bf16.bf16.f32 "
        "{%0,%1,%2,%3}, {%4,%5,%6,%7}, {%8,%9}, {%0,%1,%2,%3};"
        : "+f"(d[0]), "+f"(d[1]), "+f"(d[2]), "+f"(d[3])
        : "r"(a[0]), "r"(a[1]), "r"(a[2]), "r"(a[3]), "r"(b[0]), "r"(b[1]));
}

// ---------------- kernel 1: normalize -> bf16 (anchor pre-scaled) ----------------
__global__ void k_normalize(const float* __restrict__ A,
                            const float* __restrict__ P,
                            const float* __restrict__ N) {
    int gw   = (blockIdx.x * blockDim.x + threadIdx.x) >> 5;
    int lane = threadIdx.x & 31;
    if (gw >= 3 * BATCH) return;

    const float* src;
    __nv_bfloat16* dst;
    float scale_extra = 1.0f;
    if (gw < BATCH)          { src = A + (size_t)gw * DIM;             dst = g_an + (size_t)gw * DIM; scale_extra = SCALE_A; }
    else if (gw < 2 * BATCH) { src = P + (size_t)(gw - BATCH) * DIM;   dst = g_tn + (size_t)(gw - BATCH) * DIM; }
    else                     { src = N + (size_t)(gw - 2*BATCH) * DIM; dst = g_tn + (size_t)(gw - BATCH) * DIM; }

    float4 v0 = ((const float4*)src)[lane];
    float4 v1 = ((const float4*)src)[lane + 32];
    float s = v0.x*v0.x + v0.y*v0.y + v0.z*v0.z + v0.w*v0.w
            + v1.x*v1.x + v1.y*v1.y + v1.z*v1.z + v1.w*v1.w;
    #pragma unroll
    for (int o = 16; o; o >>= 1) s += __shfl_xor_sync(0xffffffffu, s, o);
    float inv = scale_extra / fmaxf(sqrtf(s), 1e-12f);

    __nv_bfloat162* d2 = (__nv_bfloat162*)dst;
    d2[2*lane]        = __floats2bfloat162_rn(v0.x * inv, v0.y * inv);
    d2[2*lane + 1]    = __floats2bfloat162_rn(v0.z * inv, v0.w * inv);
    d2[64 + 2*lane]   = __floats2bfloat162_rn(v1.x * inv, v1.y * inv);
    d2[64 + 2*lane+1] = __floats2bfloat162_rn(v1.z * inv, v1.w * inv);
}

// ---------------- kernel 2: exact fp32 diag (base-2 scaled) ----------------
__global__ void k_diag(const float* __restrict__ A, const float* __restrict__ P) {
    int gw   = (blockIdx.x * blockDim.x + threadIdx.x) >> 5;
    int lane = threadIdx.x & 31;
    if (gw >= BATCH) return;
    const float* a = A + (size_t)gw * DIM;
    const float* p = P + (size_t)gw * DIM;
    float4 a0 = ((const float4*)a)[lane], a1 = ((const float4*)a)[lane + 32];
    float4 p0 = ((const float4*)p)[lane], p1 = ((const float4*)p)[lane + 32];
    float saa = a0.x*a0.x + a0.y*a0.y + a0.z*a0.z + a0.w*a0.w
              + a1.x*a1.x + a1.y*a1.y + a1.z*a1.z + a1.w*a1.w;
    float spp = p0.x*p0.x + p0.y*p0.y + p0.z*p0.z + p0.w*p0.w
              + p1.x*p1.x + p1.y*p1.y + p1.z*p1.z + p1.w*p1.w;
    float sap = a0.x*p0.x + a0.y*p0.y + a0.z*p0.z + a0.w*p0.w
              + a1.x*p1.x + a1.y*p1.y + a1.z*p1.z + a1.w*p1.w;
    #pragma unroll
    for (int o = 16; o; o >>= 1) {
        saa += __shfl_xor_sync(0xffffffffu, saa, o);
        spp += __shfl_xor_sync(0xffffffffu, spp, o);
        sap += __shfl_xor_sync(0xffffffffu, sap, o);
    }
    if (lane == 0)
        g_diag[gw] = sap / (fmaxf(sqrtf(saa), 1e-12f) * (fmaxf(sqrtf(spp), 1e-12f))) * SCALE_A;
}

// ---------------- SMEM layout for GEMM ----------------
// A: [128 rows][512 B] swizzled = 64 KB at 0
// B double-buffered 64 KB each at 65536 / 131072
#define SM_B0 65536
#define SM_B1 131072
#define SMEM_TOTAL 196608

// issue one 128x256 bf16 tile via cp.async (64 KB), swizzled: chunk ^= (row&7)
__device__ __forceinline__ void issue_tile(const __nv_bfloat16* __restrict__ g,
                                           int row_base, uint32_t dst, int tid) {
    const int n    = tid >> 1;
    const int half = tid & 1;
    const char* src = (const char*)g + (size_t)(row_base + n) * 512 + half * 256;
    const uint32_t drow = dst + n * 512;
    const int r7 = n & 7;
    #pragma unroll
    for (int i = 0; i < 16; ++i) {
        int chunk = half * 16 + i;
        cp16(drow + ((chunk ^ r7) << 4), src + i * 16);
    }
}

// ---------------- kernel 3: mma.sync GEMM + fused sum-exp2 ----------------
// 256 threads = 8 warps as 4(M) x 2(N); warp tile 32x64; CTA tile 128x128.
__global__ void __launch_bounds__(256, 1) k_gemm_lse() {
    extern __shared__ __align__(128) char smem[];
    const uint32_t sb  = smem_u32(smem);
    const uint32_t smA = sb;

    const int tid  = threadIdx.x;
    const int lane = tid & 31;
    const int wid  = tid >> 5;
    const int wm   = wid & 3;     // M warp (32 rows)
    const int wn   = wid >> 2;    // N warp (64 cols)
    const int row0 = blockIdx.y * 128;
    const int col0 = blockIdx.x * COLS_PER_SPLIT;

    // ldmatrix lane->address mapping
    const int a_row_in    = lane & 15;
    const int a_chunk_add = lane >> 4;
    const int b_row_in    = (lane & 7) + ((lane >> 4) << 3);
    const int b_chunk_add = (lane >> 3) & 1;

    // prologue: A tile + B tile 0 in one cp.async group
    issue_tile(g_an, row0, smA, tid);
    issue_tile(g_tn, col0, sb + SM_B0, tid);
    asm volatile("cp.async.commit_group;" ::: "memory");

    float rs[2][2] = {{0.f, 0.f}, {0.f, 0.f}};   // per-lane row partial sums

    for (int t = 0; t < NTILES; ++t) {
        if (t + 1 < NTILES) {
            issue_tile(g_tn, col0 + (t + 1) * 128, sb + (((t + 1) & 1) ? SM_B1 : SM_B0), tid);
            asm volatile("cp.async.commit_group;" ::: "memory");
            asm volatile("cp.async.wait_group 1;" ::: "memory");
        } else {
            asm volatile("cp.async.wait_group 0;" ::: "memory");
        }
        __syncthreads();

        const uint32_t smB = sb + ((t & 1) ? SM_B1 : SM_B0);

        float acc[2][8][4];
        #pragma unroll
        for (int i = 0; i < 2; ++i)
            #pragma unroll
            for (int j = 0; j < 8; ++j)
                #pragma unroll
                for (int c = 0; c < 4; ++c) acc[i][j][c] = 0.0f;

        #pragma unroll
        for (int step = 0; step < 16; ++step) {
            uint32_t af[2][4];
            #pragma unroll
            for (int i = 0; i < 2; ++i) {
                int row   = wm * 32 + i * 16 + a_row_in;
                int chunk = (step * 2 + a_chunk_add) ^ (row & 7);
                ldsm_x4(af[i], smA + row * 512 + (chunk << 4));
            }
            uint32_t bf[4][4];
            #pragma unroll
            for (int p = 0; p < 4; ++p) {
                int row   = wn * 64 + p * 16 + b_row_in;
                int chunk = (step * 2 + b_chunk_add) ^ (row & 7);
                ldsm_x4(bf[p], smB + row * 512 + (chunk << 4));
            }
            #pragma unroll
            for (int i = 0; i < 2; ++i)
                #pragma unroll
                for (int j = 0; j < 8; ++j)
                    mma16816(acc[i][j], af[i], &bf[j >> 1][(j & 1) * 2]);
        }

        // fused epilogue: sum 2^logit (registers only)
        #pragma unroll
        for (int i = 0; i < 2; ++i) {
            float s0 = 0.f, s1 = 0.f;
            #pragma unroll
            for (int j = 0; j < 8; ++j) {
                s0 += ex2f(acc[i][j][0]) + ex2f(acc[i][j][1]);
                s1 += ex2f(acc[i][j][2]) + ex2f(acc[i][j][3]);
            }
            rs[i][0] += s0;
            rs[i][1] += s1;
        }
        __syncthreads();   // compute done before next cp.async overwrites buffer
    }

    // reduce across the 4 lanes of each quad (same rows)
    #pragma unroll
    for (int i = 0; i < 2; ++i)
        #pragma unroll
        for (int h = 0; h < 2; ++h) {
            rs[i][h] += __shfl_xor_sync(0xffffffffu, rs[i][h], 1);
            rs[i][h] += __shfl_xor_sync(0xffffffffu, rs[i][h], 2);
        }
    if ((lane & 3) == 0) {
        const int slot = blockIdx.x * 2 + wn;
        #pragma unroll
        for (int i = 0; i < 2; ++i) {
            int r = row0 + wm * 32 + i * 16 + (lane >> 2);
            g_ps[slot * BATCH + r]     = rs[i][0];
            g_ps[slot * BATCH + r + 8] = rs[i][1];
        }
    }
}

// ---------------- kernel 4/5: reduction ----------------
__global__ void k_red() {
    const int row = blockIdx.x * 256 + threadIdx.x;
    float s = 0.0f;
    #pragma unroll
    for (int j = 0; j < 4; ++j) s += g_ps[j * BATCH + row];
    float v = log2f(s) - g_diag[row];
    __shared__ double sd[256];
    sd[threadIdx.x] = (double)v;
    __syncthreads();
    #pragma unroll
    for (int k = 128; k > 0; k >>= 1) {
        if (threadIdx.x < k) sd[threadIdx.x] += sd[threadIdx.x + k];
        __syncthreads();
    }
    if (threadIdx.x == 0) g_bsum[blockIdx.x] = sd[0];
}

__global__ void k_fin(float* __restrict__ out) {
    double v = g_bsum[threadIdx.x];
    #pragma unroll
    for (int o = 16; o; o >>= 1) v += __shfl_xor_sync(0xffffffffu, v, o);
    if (threadIdx.x == 0) out[0] = (float)(v * LN2_D / (double)BATCH);
}

// ---------------- launcher ----------------
extern "C" void kernel_launch(void* const* d_in, const int* in_sizes, int n_in,
                              void* d_out, int out_size) {
    const float* A = (const float*)d_in[0];
    const float* P = (const float*)d_in[1];
    const float* N = (const float*)d_in[2];
    float* out = (float*)d_out;

    cudaFuncSetAttribute(k_gemm_lse, cudaFuncAttributeMaxDynamicSharedMemorySize,
                         SMEM_TOTAL);

    k_normalize<<<(3 * BATCH) / 8, 256>>>(A, P, N);
    k_diag<<<BATCH / 8, 256>>>(A, P);
    k_gemm_lse<<<dim3(COLSPLIT, BATCH / 128), 256, SMEM_TOTAL>>>();
    k_red<<<32, 256>>>();
    k_fin<<<1, 32>>>(out);
}

// round 4
// speedup vs baseline: 9.9662x; 1.7167x over previous
#include <cuda_runtime.h>
#include <cuda_bf16.h>
#include <cstdint>

// ---------------- problem constants ----------------
#define BATCH 8192
#define DIM   256
#define TGT   16384
#define COLSPLIT 4
#define COLS_PER_SPLIT (TGT / COLSPLIT)   // 4096
#define NTILES (COLS_PER_SPLIT / 128)     // 32 B-tiles per CTA
#define ROWS_CTA 256
#define SCALE_A 28.8539008177792681f      // (1/0.05) * log2(e)
#define LN2_D   0.69314718055994530942

// ---------------- scratch (device globals) ----------------
__device__ __align__(1024) __nv_bfloat16 g_an[BATCH * DIM];
__device__ __align__(1024) __nv_bfloat16 g_tn[TGT * DIM];
__device__ float  g_diag[BATCH];
__device__ float  g_ps[8 * BATCH];
__device__ double g_bsum[32];

// ---------------- helpers ----------------
__device__ __forceinline__ uint32_t smem_u32(const void* p) {
    uint32_t a;
    asm("{ .reg .u64 t; cvta.to.shared.u64 t, %1; cvt.u32.u64 %0, t; }" : "=r"(a) : "l"(p));
    return a;
}
__device__ __forceinline__ float ex2f(float x) {
    float y; asm("ex2.approx.f32 %0, %1;" : "=f"(y) : "f"(x)); return y;
}
__device__ __forceinline__ void ldsm_x4(uint32_t* r, uint32_t addr) {
    asm volatile("ldmatrix.sync.aligned.m8n8.x4.shared.b16 {%0,%1,%2,%3}, [%4];"
        : "=r"(r[0]), "=r"(r[1]), "=r"(r[2]), "=r"(r[3]) : "r"(addr));
}
__device__ __forceinline__ void mma16816(float* d, const uint32_t* a, const uint32_t* b) {
    asm volatile("mma.sync.aligned.m16n8k16.row.col.f32.bf16.bf16.f32 "
        "{%0,%1,%2,%3}, {%4,%5,%6,%7}, {%8,%9}, {%0,%1,%2,%3};"
        : "+f"(d[0]), "+f"(d[1]), "+f"(d[2]), "+f"(d[3])
        : "r"(a[0]), "r"(a[1]), "r"(a[2]), "r"(a[3]), "r"(b[0]), "r"(b[1]));
}
__device__ __forceinline__ void bulk_g2s(uint32_t dst, const void* src,
                                         uint32_t bytes, uint32_t mbar) {
    asm volatile("cp.async.bulk.shared::cluster.global.mbarrier::complete_tx::bytes "
                 "[%0], [%1], %2, [%3];"
                 :: "r"(dst), "l"(src), "r"(bytes), "r"(mbar) : "memory");
}
#define MBAR_INIT(a, c) asm volatile("mbarrier.init.shared.b64 [%0], %1;" :: "r"(a), "r"((uint32_t)(c)) : "memory")
#define MBAR_ARRIVE_TX(a, tx) asm volatile("mbarrier.arrive.expect_tx.shared.b64 _, [%0], %1;" :: "r"(a), "r"((uint32_t)(tx)) : "memory")
#define MBAR_WAIT(addr, parity) do {                                              \
    uint32_t _m = (addr); uint32_t _p = (parity); uint32_t _d;                    \
    asm volatile("{ .reg .pred p;\n\t"                                            \
        "mbarrier.try_wait.parity.acquire.cta.shared::cta.b64 p, [%1], %2;\n\t"   \
        "selp.b32 %0, 1, 0, p; }" : "=r"(_d) : "r"(_m), "r"(_p) : "memory");      \
    if (!_d) {                                                                    \
        asm volatile("{ .reg .pred P1;\n\t"                                       \
            "WL_%=:\n\t"                                                          \
            "mbarrier.try_wait.parity.acquire.cta.shared::cta.b64 P1, [%0], %1, 0x989680;\n\t" \
            "@P1 bra.uni WD_%=;\n\t"                                              \
            "bra.uni WL_%=;\n\t"                                                  \
            "WD_%=: }" :: "r"(_m), "r"(_p) : "memory");                           \
    }                                                                             \
} while (0)

// ---------------- kernel 1: normalize -> bf16 (anchor pre-scaled) ----------------
__global__ void k_normalize(const float* __restrict__ A,
                            const float* __restrict__ P,
                            const float* __restrict__ N) {
    int gw   = (blockIdx.x * blockDim.x + threadIdx.x) >> 5;
    int lane = threadIdx.x & 31;
    if (gw >= 3 * BATCH) return;

    const float* src;
    __nv_bfloat16* dst;
    float scale_extra = 1.0f;
    if (gw < BATCH)          { src = A + (size_t)gw * DIM;             dst = g_an + (size_t)gw * DIM; scale_extra = SCALE_A; }
    else if (gw < 2 * BATCH) { src = P + (size_t)(gw - BATCH) * DIM;   dst = g_tn + (size_t)(gw - BATCH) * DIM; }
    else                     { src = N + (size_t)(gw - 2*BATCH) * DIM; dst = g_tn + (size_t)(gw - BATCH) * DIM; }

    float4 v0 = ((const float4*)src)[lane];
    float4 v1 = ((const float4*)src)[lane + 32];
    float s = v0.x*v0.x + v0.y*v0.y + v0.z*v0.z + v0.w*v0.w
            + v1.x*v1.x + v1.y*v1.y + v1.z*v1.z + v1.w*v1.w;
    #pragma unroll
    for (int o = 16; o; o >>= 1) s += __shfl_xor_sync(0xffffffffu, s, o);
    float inv = scale_extra / fmaxf(sqrtf(s), 1e-12f);

    __nv_bfloat162* d2 = (__nv_bfloat162*)dst;
    d2[2*lane]        = __floats2bfloat162_rn(v0.x * inv, v0.y * inv);
    d2[2*lane + 1]    = __floats2bfloat162_rn(v0.z * inv, v0.w * inv);
    d2[64 + 2*lane]   = __floats2bfloat162_rn(v1.x * inv, v1.y * inv);
    d2[64 + 2*lane+1] = __floats2bfloat162_rn(v1.z * inv, v1.w * inv);
}

// ---------------- kernel 2: exact fp32 diag (base-2 scaled) ----------------
__global__ void k_diag(const float* __restrict__ A, const float* __restrict__ P) {
    int gw   = (blockIdx.x * blockDim.x + threadIdx.x) >> 5;
    int lane = threadIdx.x & 31;
    if (gw >= BATCH) return;
    const float* a = A + (size_t)gw * DIM;
    const float* p = P + (size_t)gw * DIM;
    float4 a0 = ((const float4*)a)[lane], a1 = ((const float4*)a)[lane + 32];
    float4 p0 = ((const float4*)p)[lane], p1 = ((const float4*)p)[lane + 32];
    float saa = a0.x*a0.x + a0.y*a0.y + a0.z*a0.z + a0.w*a0.w
              + a1.x*a1.x + a1.y*a1.y + a1.z*a1.z + a1.w*a1.w;
    float spp = p0.x*p0.x + p0.y*p0.y + p0.z*p0.z + p0.w*p0.w
              + p1.x*p1.x + p1.y*p1.y + p1.z*p1.z + p1.w*p1.w;
    float sap = a0.x*p0.x + a0.y*p0.y + a0.z*p0.z + a0.w*p0.w
              + a1.x*p1.x + a1.y*p1.y + a1.z*p1.z + a1.w*p1.w;
    #pragma unroll
    for (int o = 16; o; o >>= 1) {
        saa += __shfl_xor_sync(0xffffffffu, saa, o);
        spp += __shfl_xor_sync(0xffffffffu, spp, o);
        sap += __shfl_xor_sync(0xffffffffu, sap, o);
    }
    if (lane == 0)
        g_diag[gw] = sap / (fmaxf(sqrtf(saa), 1e-12f) * fmaxf(sqrtf(spp), 1e-12f)) * SCALE_A;
}

// ---------------- SMEM layout ----------------
// A: 256 rows, stride 528 B (512 data + 16 skew)  -> conflict-free LDSM
// B: 2 buffers, 128 rows, stride 272 B (256 data + 16 skew)
#define A_STRIDE 528
#define B_STRIDE 272
#define SM_A   0
#define SM_B0  (ROWS_CTA * A_STRIDE)            // 135168
#define SM_B1  (SM_B0 + 128 * B_STRIDE)         // 169984
#define MB_A   (SM_B1 + 128 * B_STRIDE)         // 204800
#define MB_B0  (MB_A + 8)
#define MB_B1  (MB_A + 16)
#define SMEM_TOTAL (MB_A + 32)

// ---------------- kernel 3: mma.sync GEMM + fused sum-exp2 ----------------
// 256 threads = 8 warps as 4(M) x 2(N); warp tile 64x64; CTA tile 256x128.
__global__ void __launch_bounds__(256, 1) k_gemm_lse() {
    extern __shared__ __align__(128) char smem[];
    const uint32_t sb  = smem_u32(smem);
    const uint32_t smA = sb + SM_A;

    const int tid  = threadIdx.x;
    const int lane = tid & 31;
    const int wid  = tid >> 5;
    const int wm   = wid & 3;     // M warp (64 rows)
    const int wn   = wid >> 2;    // N warp (64 cols)
    const int row0 = blockIdx.y * ROWS_CTA;
    const int col0 = blockIdx.x * COLS_PER_SPLIT;

    const int a_row_in    = lane & 15;
    const int a_chunk_add = lane >> 4;
    const int b_row_in    = (lane & 7) + ((lane >> 4) << 3);
    const int b_chunk_add = (lane >> 3) & 1;

    if (tid == 0) {
        MBAR_INIT(sb + MB_A, 256);
        MBAR_INIT(sb + MB_B0, 128);
        MBAR_INIT(sb + MB_B1, 128);
    }
    __syncthreads();

    // prologue: A rows (512 B each) + first two B K-half chunks (256 B rows)
    {
        MBAR_ARRIVE_TX(sb + MB_A, 512);
        const char* srcA = (const char*)g_an + (size_t)(row0 + tid) * 512;
        bulk_g2s(smA + tid * A_STRIDE, srcA, 512, sb + MB_A);

        if (tid < 128) {
            MBAR_ARRIVE_TX(sb + MB_B0, 256);
            const char* s0 = (const char*)g_tn + (size_t)(col0 + tid) * 512;
            bulk_g2s(sb + SM_B0 + tid * B_STRIDE, s0, 256, sb + MB_B0);
        } else {
            int it = tid - 128;
            MBAR_ARRIVE_TX(sb + MB_B1, 256);
            const char* s1 = (const char*)g_tn + (size_t)(col0 + it) * 512 + 256;
            bulk_g2s(sb + SM_B1 + it * B_STRIDE, s1, 256, sb + MB_B1);
        }
    }
    MBAR_WAIT(sb + MB_A, 0);

    float rs[4][2];
    #pragma unroll
    for (int i = 0; i < 4; ++i) { rs[i][0] = 0.f; rs[i][1] = 0.f; }

    int ph0 = 0, ph1 = 0;

    for (int t = 0; t < NTILES; ++t) {
        float acc[4][8][4];
        #pragma unroll
        for (int i = 0; i < 4; ++i)
            #pragma unroll
            for (int j = 0; j < 8; ++j)
                #pragma unroll
                for (int c = 0; c < 4; ++c) acc[i][j][c] = 0.0f;

        #pragma unroll
        for (int h = 0; h < 2; ++h) {
            const uint32_t smB = sb + (h ? SM_B1 : SM_B0);
            const uint32_t mb  = sb + (h ? MB_B1 : MB_B0);
            if (h) { MBAR_WAIT(mb, ph1); ph1 ^= 1; }
            else   { MBAR_WAIT(mb, ph0); ph0 ^= 1; }

            #pragma unroll
            for (int step = 0; step < 8; ++step) {
                uint32_t af[4][4];
                #pragma unroll
                for (int i = 0; i < 4; ++i) {
                    int row   = wm * 64 + i * 16 + a_row_in;
                    int chunk = (h * 8 + step) * 2 + a_chunk_add;
                    ldsm_x4(af[i], smA + row * A_STRIDE + (chunk << 4));
                }
                uint32_t bf[4][4];
                #pragma unroll
                for (int p = 0; p < 4; ++p) {
                    int row   = wn * 64 + p * 16 + b_row_in;
                    int chunk = step * 2 + b_chunk_add;
                    ldsm_x4(bf[p], smB + row * B_STRIDE + (chunk << 4));
                }
                #pragma unroll
                for (int i = 0; i < 4; ++i)
                    #pragma unroll
                    for (int j = 0; j < 8; ++j)
                        mma16816(acc[i][j], af[i], &bf[j >> 1][(j & 1) * 2]);
            }

            __syncthreads();   // all warps done reading this B buffer
            if (t + 1 < NTILES) {
                if (!h && tid < 128) {
                    MBAR_ARRIVE_TX(mb, 256);
                    const char* s = (const char*)g_tn
                        + (size_t)(col0 + (t + 1) * 128 + tid) * 512;
                    bulk_g2s(smB + tid * B_STRIDE, s, 256, mb);
                } else if (h && tid >= 128) {
                    int it = tid - 128;
                    MBAR_ARRIVE_TX(mb, 256);
                    const char* s = (const char*)g_tn
                        + (size_t)(col0 + (t + 1) * 128 + it) * 512 + 256;
                    bulk_g2s(smB + it * B_STRIDE, s, 256, mb);
                }
            }
        }

        // fused epilogue: sum 2^logit
        #pragma unroll
        for (int i = 0; i < 4; ++i) {
            float s0 = 0.f, s1 = 0.f;
            #pragma unroll
            for (int j = 0; j < 8; ++j) {
                s0 += ex2f(acc[i][j][0]) + ex2f(acc[i][j][1]);
                s1 += ex2f(acc[i][j][2]) + ex2f(acc[i][j][3]);
            }
            rs[i][0] += s0;
            rs[i][1] += s1;
        }
    }

    // quad reduce (lanes sharing rows)
    #pragma unroll
    for (int i = 0; i < 4; ++i)
        #pragma unroll
        for (int hh = 0; hh < 2; ++hh) {
            rs[i][hh] += __shfl_xor_sync(0xffffffffu, rs[i][hh], 1);
            rs[i][hh] += __shfl_xor_sync(0xffffffffu, rs[i][hh], 2);
        }
    if ((lane & 3) == 0) {
        const int slot = blockIdx.x * 2 + wn;   // 0..7
        #pragma unroll
        for (int i = 0; i < 4; ++i) {
            int r = row0 + wm * 64 + i * 16 + (lane >> 2);
            g_ps[slot * BATCH + r]     = rs[i][0];
            g_ps[slot * BATCH + r + 8] = rs[i][1];
        }
    }
}

// ---------------- kernel 4/5: reduction ----------------
__global__ void k_red() {
    const int row = blockIdx.x * 256 + threadIdx.x;
    float s = 0.0f;
    #pragma unroll
    for (int j = 0; j < 8; ++j) s += g_ps[j * BATCH + row];
    float v = log2f(s) - g_diag[row];
    __shared__ double sd[256];
    sd[threadIdx.x] = (double)v;
    __syncthreads();
    #pragma unroll
    for (int k = 128; k > 0; k >>= 1) {
        if (threadIdx.x < k) sd[threadIdx.x] += sd[threadIdx.x + k];
        __syncthreads();
    }
    if (threadIdx.x == 0) g_bsum[blockIdx.x] = sd[0];
}

__global__ void k_fin(float* __restrict__ out) {
    double v = g_bsum[threadIdx.x];
    #pragma unroll
    for (int o = 16; o; o >>= 1) v += __shfl_xor_sync(0xffffffffu, v, o);
    if (threadIdx.x == 0) out[0] = (float)(v * LN2_D / (double)BATCH);
}

// ---------------- launcher ----------------
extern "C" void kernel_launch(void* const* d_in, const int* in_sizes, int n_in,
                              void* d_out, int out_size) {
    const float* A = (const float*)d_in[0];
    const float* P = (const float*)d_in[1];
    const float* N = (const float*)d_in[2];
    float* out = (float*)d_out;

    cudaFuncSetAttribute(k_gemm_lse, cudaFuncAttributeMaxDynamicSharedMemorySize,
                         SMEM_TOTAL);

    k_normalize<<<(3 * BATCH) / 8, 256>>>(A, P, N);
    k_diag<<<BATCH / 8, 256>>>(A, P);
    k_gemm_lse<<<dim3(COLSPLIT, BATCH / ROWS_CTA), 256, SMEM_TOTAL>>>();
    k_red<<<32, 256>>>();
    k_fin<<<1, 32>>>(out);
}